// round 2
// baseline (speedup 1.0000x reference)
#include <cuda_runtime.h>
#include <math.h>

// Problem constants (fixed by the bench: B=8, H=W=128, C=192, split=(8,16), heads=8)
#define BB   8
#define HH   128
#define WW   128
#define CC   192
#define LL   (HH * WW)          // 16384
#define MM   (BB * LL)          // 131072 rows
#define CHH  96                 // C/2 per branch
#define NHH  4                  // heads per branch
#define DD   24                 // head dim
#define EPSV 1e-5f
#define SCALE 0.20412414523193154f   // 24^-0.5

// ---------------------------------------------------------------------------
// Scratch arena (no allocations allowed). Offsets in floats.
//   q1   : MM*CC
//   v1   : MM*CC
//   k2   : MM*CC
//   v2   : MM*CC
//   att  : MM*CC
//   conv : MM*CC
//   hid  : MM*96
//   gate : MM
//   w1t  : 192*96
// ---------------------------------------------------------------------------
#define OFF_Q1   ((size_t)0)
#define OFF_V1   (OFF_Q1  + (size_t)MM * CC)
#define OFF_K2   (OFF_V1  + (size_t)MM * CC)
#define OFF_V2   (OFF_K2  + (size_t)MM * CC)
#define OFF_ATT  (OFF_V2  + (size_t)MM * CC)
#define OFF_CONV (OFF_ATT + (size_t)MM * CC)
#define OFF_HID  (OFF_CONV + (size_t)MM * CC)
#define OFF_GATE (OFF_HID + (size_t)MM * 96)
#define OFF_W1T  (OFF_GATE + (size_t)MM)
#define SCRATCH_FLOATS (OFF_W1T + (size_t)192 * 96)

__device__ float g_scratch[SCRATCH_FLOATS];

// ---------------------------------------------------------------------------
// Generic SGEMM, K fixed at 192. C[m,n] = gate[m] * (A[m,:] @ B[:,n]) + bias[n]
// A: M x 192 row-major (lda). B: 192 x N row-major (ldb), pointer may be
// pre-offset into a wider matrix. 64x64 tile, BK=16, 256 threads, 4x4 micro.
// ---------------------------------------------------------------------------
__global__ __launch_bounds__(256) void sgemm192(
    const float* __restrict__ A, int lda,
    const float* __restrict__ Bm, int ldb,
    const float* __restrict__ bias,
    const float* __restrict__ gate,
    float* __restrict__ Cout, int ldc, int N)
{
    __shared__ float As[16][65];   // padded, stored transposed
    __shared__ float Bs[16][64];

    const int bm = blockIdx.x * 64;
    const int bn = blockIdx.y * 64;
    const int tid = threadIdx.x;

    const int arow = tid >> 2;             // 0..63
    const int acol = (tid & 3) << 2;       // 0,4,8,12
    const int brow = tid >> 4;             // 0..15
    const int bcol = (tid & 15) << 2;      // 0..60
    const int tx = tid & 15;               // n direction
    const int ty = tid >> 4;               // m direction

    float acc[4][4] = {};

    const float* Aptr = A + (size_t)(bm + arow) * lda + acol;

    for (int k0 = 0; k0 < 192; k0 += 16) {
        float4 av = *(const float4*)(Aptr + k0);
        As[acol + 0][arow] = av.x;
        As[acol + 1][arow] = av.y;
        As[acol + 2][arow] = av.z;
        As[acol + 3][arow] = av.w;

        float4 bv = make_float4(0.f, 0.f, 0.f, 0.f);
        if (bn + bcol < N)
            bv = *(const float4*)&Bm[(size_t)(k0 + brow) * ldb + bn + bcol];
        *(float4*)&Bs[brow][bcol] = bv;

        __syncthreads();

        #pragma unroll
        for (int k = 0; k < 16; k++) {
            float a0 = As[k][ty * 4 + 0];
            float a1 = As[k][ty * 4 + 1];
            float a2 = As[k][ty * 4 + 2];
            float a3 = As[k][ty * 4 + 3];
            float4 bq = *(const float4*)&Bs[k][tx * 4];
            acc[0][0] += a0 * bq.x; acc[0][1] += a0 * bq.y; acc[0][2] += a0 * bq.z; acc[0][3] += a0 * bq.w;
            acc[1][0] += a1 * bq.x; acc[1][1] += a1 * bq.y; acc[1][2] += a1 * bq.z; acc[1][3] += a1 * bq.w;
            acc[2][0] += a2 * bq.x; acc[2][1] += a2 * bq.y; acc[2][2] += a2 * bq.z; acc[2][3] += a2 * bq.w;
            acc[3][0] += a3 * bq.x; acc[3][1] += a3 * bq.y; acc[3][2] += a3 * bq.z; acc[3][3] += a3 * bq.w;
        }
        __syncthreads();
    }

    const int n = bn + tx * 4;
    if (n < N) {
        float bx = bias ? bias[n + 0] : 0.f;
        float by = bias ? bias[n + 1] : 0.f;
        float bz = bias ? bias[n + 2] : 0.f;
        float bw = bias ? bias[n + 3] : 0.f;
        #pragma unroll
        for (int i = 0; i < 4; i++) {
            int m = bm + ty * 4 + i;
            float g = gate ? gate[m] : 1.0f;
            float4 o;
            o.x = acc[i][0] * g + bx;
            o.y = acc[i][1] * g + by;
            o.z = acc[i][2] * g + bz;
            o.w = acc[i][3] * g + bw;
            *(float4*)&Cout[(size_t)m * ldc + n] = o;
        }
    }
}

// ---------------------------------------------------------------------------
// Window attention. One block = (window, head, batch*branch).
// 128 tokens per window (8x16 or 16x8), head dim 24, online softmax.
// q from x-qkv, k from y-qkv, v from x-qkv. Writes att (B,L,C) directly.
// ---------------------------------------------------------------------------
__global__ __launch_bounds__(128) void win_attn(
    const float* __restrict__ q, const float* __restrict__ k,
    const float* __restrict__ v, float* __restrict__ out)
{
    __shared__ float Ks[128][DD];
    __shared__ float Vs[128][DD];

    const int wid  = blockIdx.x;      // 0..127 window within image+branch
    const int head = blockIdx.y;      // 0..3
    const int z    = blockIdx.z;      // 0..15
    const int b  = z >> 1;
    const int br = z & 1;

    const int Hs  = br ? 16 : 8;
    const int Wsp = br ? 8 : 16;
    const int nWw = WW / Wsp;
    const int wy = wid / nWw, wx = wid % nWw;
    const int h0 = wy * Hs, w0 = wx * Wsp;
    const int cb = br * CHH + head * DD;
    const int tid = threadIdx.x;

    // cooperative K,V load
    for (int idx = tid; idx < 128 * DD; idx += 128) {
        int t = idx / DD, d = idx - t * DD;
        int hs = t / Wsp, ws = t - hs * Wsp;
        int l = (h0 + hs) * WW + (w0 + ws);
        size_t base = ((size_t)b * LL + l) * CC + cb + d;
        Ks[t][d] = k[base];
        Vs[t][d] = v[base];
    }
    __syncthreads();

    // own query row
    const int hs = tid / Wsp, ws = tid - hs * Wsp;
    const int l = (h0 + hs) * WW + (w0 + ws);
    const size_t qbase = ((size_t)b * LL + l) * CC + cb;

    float qreg[DD];
    #pragma unroll
    for (int d = 0; d < DD; d++) qreg[d] = q[qbase + d] * SCALE;

    float mrun = -1e30f, lsum = 0.f;
    float acc[DD];
    #pragma unroll
    for (int d = 0; d < DD; d++) acc[d] = 0.f;

    for (int j = 0; j < 128; j++) {
        float s = 0.f;
        #pragma unroll
        for (int d = 0; d < DD; d++) s += qreg[d] * Ks[j][d];
        if (s > mrun) {                       // rare after warm-up
            float corr = __expf(mrun - s);
            lsum *= corr;
            #pragma unroll
            for (int d = 0; d < DD; d++) acc[d] *= corr;
            mrun = s;
        }
        float p = __expf(s - mrun);
        lsum += p;
        #pragma unroll
        for (int d = 0; d < DD; d++) acc[d] += p * Vs[j][d];
    }

    float inv = 1.f / lsum;
    #pragma unroll
    for (int d = 0; d < DD; d++) out[qbase + d] = acc[d] * inv;
}

// ---------------------------------------------------------------------------
// Depthwise 3x3 conv (SAME) + bias + BN + exact GELU, channel-last layout.
// ---------------------------------------------------------------------------
__global__ __launch_bounds__(256) void dwconv_bn_gelu(
    const float* __restrict__ x, const float* __restrict__ wgt,
    const float* __restrict__ wb,
    const float* __restrict__ g1, const float* __restrict__ b1,
    const float* __restrict__ m1, const float* __restrict__ v1r,
    float* __restrict__ out)
{
    int idx = blockIdx.x * 256 + threadIdx.x;
    if (idx >= MM * CC) return;
    int c = idx % CC;
    int rem = idx / CC;
    int l = rem % LL;
    int b = rem / LL;
    int h = l >> 7, w = l & 127;

    float acc = 0.f;
    #pragma unroll
    for (int kh = 0; kh < 3; kh++) {
        int hh = h + kh - 1;
        if ((unsigned)hh >= (unsigned)HH) continue;
        #pragma unroll
        for (int kw = 0; kw < 3; kw++) {
            int ww = w + kw - 1;
            if ((unsigned)ww >= (unsigned)WW) continue;
            acc += x[((size_t)b * LL + hh * WW + ww) * CC + c] * wgt[c * 9 + kh * 3 + kw];
        }
    }
    acc += wb[c];
    float sc = g1[c] * rsqrtf(v1r[c] + EPSV);
    float t = (acc - m1[c]) * sc + b1[c];
    out[idx] = 0.5f * t * (1.f + erff(t * 0.70710678118654752f));
}

// ---------------------------------------------------------------------------
// Transpose si_w1 (96,192) -> (192,96) so the 1x1 conv runs through sgemm192.
// ---------------------------------------------------------------------------
__global__ void transpose_w1(const float* __restrict__ w1, float* __restrict__ w1t)
{
    int idx = blockIdx.x * 256 + threadIdx.x;
    if (idx >= 96 * 192) return;
    int j = idx / 192, c = idx - j * 192;
    w1t[c * 96 + j] = w1[idx];
}

// ---------------------------------------------------------------------------
// gate[m] = sigmoid( sum_j si_w2[j] * gelu(bn2(hid[m,j])) + si_b2 )
// One warp per pixel (hid already includes si_b1 via GEMM bias).
// ---------------------------------------------------------------------------
__global__ __launch_bounds__(128) void gate_kernel(
    const float* __restrict__ hid,
    const float* __restrict__ g2, const float* __restrict__ b2,
    const float* __restrict__ m2, const float* __restrict__ v2r,
    const float* __restrict__ w2, const float* __restrict__ sb2,
    float* __restrict__ gate)
{
    int m = blockIdx.x * 4 + (threadIdx.x >> 5);
    int lane = threadIdx.x & 31;
    float sum = 0.f;
    #pragma unroll
    for (int jj = 0; jj < 3; jj++) {
        int j = lane + jj * 32;
        float t = hid[(size_t)m * 96 + j];
        float sc = g2[j] * rsqrtf(v2r[j] + EPSV);
        t = (t - m2[j]) * sc + b2[j];
        t = 0.5f * t * (1.f + erff(t * 0.70710678118654752f));
        sum += t * w2[j];
    }
    #pragma unroll
    for (int o = 16; o; o >>= 1) sum += __shfl_xor_sync(0xffffffffu, sum, o);
    if (lane == 0) {
        float s = sum + sb2[0];
        gate[m] = 1.f / (1.f + __expf(-s));
    }
}

// ---------------------------------------------------------------------------
extern "C" void kernel_launch(void* const* d_in, const int* in_sizes, int n_in,
                              void* d_out, int out_size)
{
    const float* x     = (const float*)d_in[0];
    const float* y     = (const float*)d_in[1];
    const float* Wqkv  = (const float*)d_in[2];
    const float* bqkv  = (const float*)d_in[3];
    const float* dw_w  = (const float*)d_in[4];
    const float* dw_b  = (const float*)d_in[5];
    const float* bn1_g = (const float*)d_in[6];
    const float* bn1_b = (const float*)d_in[7];
    const float* bn1_m = (const float*)d_in[8];
    const float* bn1_v = (const float*)d_in[9];
    const float* si_w1 = (const float*)d_in[10];
    const float* si_b1 = (const float*)d_in[11];
    const float* bn2_g = (const float*)d_in[12];
    const float* bn2_b = (const float*)d_in[13];
    const float* bn2_m = (const float*)d_in[14];
    const float* bn2_v = (const float*)d_in[15];
    const float* si_w2 = (const float*)d_in[16];
    const float* si_b2 = (const float*)d_in[17];
    const float* projw = (const float*)d_in[18];
    const float* projb = (const float*)d_in[19];

    float* scratch = nullptr;
    cudaGetSymbolAddress((void**)&scratch, g_scratch);

    float* q1   = scratch + OFF_Q1;
    float* v1   = scratch + OFF_V1;
    float* k2   = scratch + OFF_K2;
    float* v2   = scratch + OFF_V2;
    float* att  = scratch + OFF_ATT;
    float* conv = scratch + OFF_CONV;
    float* hid  = scratch + OFF_HID;
    float* gate = scratch + OFF_GATE;
    float* w1t  = scratch + OFF_W1T;

    dim3 gemmGrid(MM / 64, 3);

    // qkv projections (only the 4 needed slices)
    sgemm192<<<gemmGrid, 256>>>(x, CC, Wqkv + 0,       3 * CC, bqkv + 0,       nullptr, q1, CC, CC);
    sgemm192<<<gemmGrid, 256>>>(x, CC, Wqkv + 2 * CC,  3 * CC, bqkv + 2 * CC,  nullptr, v1, CC, CC);
    sgemm192<<<gemmGrid, 256>>>(y, CC, Wqkv + CC,      3 * CC, bqkv + CC,      nullptr, k2, CC, CC);
    sgemm192<<<gemmGrid, 256>>>(y, CC, Wqkv + 2 * CC,  3 * CC, bqkv + 2 * CC,  nullptr, v2, CC, CC);

    // window attention (both branches, all heads)
    win_attn<<<dim3(128, NHH, BB * 2), 128>>>(q1, k2, v1, att);

    // conv gating path on v2
    dwconv_bn_gelu<<<(MM * CC + 255) / 256, 256>>>(v2, dw_w, dw_b,
                                                   bn1_g, bn1_b, bn1_m, bn1_v, conv);
    transpose_w1<<<(96 * 192 + 255) / 256, 256>>>(si_w1, w1t);
    sgemm192<<<dim3(MM / 64, 2), 256>>>(conv, CC, w1t, 96, si_b1, nullptr, hid, 96, 96);
    gate_kernel<<<MM / 4, 128>>>(hid, bn2_g, bn2_b, bn2_m, bn2_v, si_w2, si_b2, gate);

    // final projection with fused per-row sigmoid gate
    sgemm192<<<gemmGrid, 256>>>(att, CC, projw, CC, projb, gate, (float*)d_out, CC, CC);
}

// round 3
// speedup vs baseline: 1.0006x; 1.0006x over previous
#include <cuda_runtime.h>
#include <math.h>

// Problem constants (fixed by the bench: B=8, H=W=128, C=192, split=(8,16), heads=8)
#define BB   8
#define HH   128
#define WW   128
#define CC   192
#define LL   (HH * WW)          // 16384
#define MM   (BB * LL)          // 131072 rows
#define CHH  96                 // C/2 per branch
#define NHH  4                  // heads per branch
#define DD   24                 // head dim
#define EPSV 1e-5f
#define SCALE 0.20412414523193154f   // 24^-0.5

// ---------------------------------------------------------------------------
// Scratch arena (no allocations allowed). Offsets in floats.
//   q1   : MM*CC
//   v1   : MM*CC
//   k2   : MM*CC
//   v2   : MM*CC
//   att  : MM*CC
//   conv : MM*CC
//   hid  : MM*96
//   gate : MM
//   w1t  : 192*96
// ---------------------------------------------------------------------------
#define OFF_Q1   ((size_t)0)
#define OFF_V1   (OFF_Q1  + (size_t)MM * CC)
#define OFF_K2   (OFF_V1  + (size_t)MM * CC)
#define OFF_V2   (OFF_K2  + (size_t)MM * CC)
#define OFF_ATT  (OFF_V2  + (size_t)MM * CC)
#define OFF_CONV (OFF_ATT + (size_t)MM * CC)
#define OFF_HID  (OFF_CONV + (size_t)MM * CC)
#define OFF_GATE (OFF_HID + (size_t)MM * 96)
#define OFF_W1T  (OFF_GATE + (size_t)MM)
#define SCRATCH_FLOATS (OFF_W1T + (size_t)192 * 96)

__device__ float g_scratch[SCRATCH_FLOATS];

// ---------------------------------------------------------------------------
// Generic SGEMM, K fixed at 192. C[m,n] = gate[m] * (A[m,:] @ B[:,n]) + bias[n]
// A: M x 192 row-major (lda). B: 192 x N row-major (ldb), pointer may be
// pre-offset into a wider matrix. 64x64 tile, BK=16, 256 threads, 4x4 micro.
// ---------------------------------------------------------------------------
__global__ __launch_bounds__(256) void sgemm192(
    const float* __restrict__ A, int lda,
    const float* __restrict__ Bm, int ldb,
    const float* __restrict__ bias,
    const float* __restrict__ gate,
    float* __restrict__ Cout, int ldc, int N)
{
    __shared__ float As[16][65];   // padded, stored transposed
    __shared__ float Bs[16][64];

    const int bm = blockIdx.x * 64;
    const int bn = blockIdx.y * 64;
    const int tid = threadIdx.x;

    const int arow = tid >> 2;             // 0..63
    const int acol = (tid & 3) << 2;       // 0,4,8,12
    const int brow = tid >> 4;             // 0..15
    const int bcol = (tid & 15) << 2;      // 0..60
    const int tx = tid & 15;               // n direction
    const int ty = tid >> 4;               // m direction

    float acc[4][4] = {};

    const float* Aptr = A + (size_t)(bm + arow) * lda + acol;

    for (int k0 = 0; k0 < 192; k0 += 16) {
        float4 av = *(const float4*)(Aptr + k0);
        As[acol + 0][arow] = av.x;
        As[acol + 1][arow] = av.y;
        As[acol + 2][arow] = av.z;
        As[acol + 3][arow] = av.w;

        float4 bv = make_float4(0.f, 0.f, 0.f, 0.f);
        if (bn + bcol < N)
            bv = *(const float4*)&Bm[(size_t)(k0 + brow) * ldb + bn + bcol];
        *(float4*)&Bs[brow][bcol] = bv;

        __syncthreads();

        #pragma unroll
        for (int k = 0; k < 16; k++) {
            float a0 = As[k][ty * 4 + 0];
            float a1 = As[k][ty * 4 + 1];
            float a2 = As[k][ty * 4 + 2];
            float a3 = As[k][ty * 4 + 3];
            float4 bq = *(const float4*)&Bs[k][tx * 4];
            acc[0][0] += a0 * bq.x; acc[0][1] += a0 * bq.y; acc[0][2] += a0 * bq.z; acc[0][3] += a0 * bq.w;
            acc[1][0] += a1 * bq.x; acc[1][1] += a1 * bq.y; acc[1][2] += a1 * bq.z; acc[1][3] += a1 * bq.w;
            acc[2][0] += a2 * bq.x; acc[2][1] += a2 * bq.y; acc[2][2] += a2 * bq.z; acc[2][3] += a2 * bq.w;
            acc[3][0] += a3 * bq.x; acc[3][1] += a3 * bq.y; acc[3][2] += a3 * bq.z; acc[3][3] += a3 * bq.w;
        }
        __syncthreads();
    }

    const int n = bn + tx * 4;
    if (n < N) {
        float bx = bias ? bias[n + 0] : 0.f;
        float by = bias ? bias[n + 1] : 0.f;
        float bz = bias ? bias[n + 2] : 0.f;
        float bw = bias ? bias[n + 3] : 0.f;
        #pragma unroll
        for (int i = 0; i < 4; i++) {
            int m = bm + ty * 4 + i;
            float g = gate ? gate[m] : 1.0f;
            float4 o;
            o.x = acc[i][0] * g + bx;
            o.y = acc[i][1] * g + by;
            o.z = acc[i][2] * g + bz;
            o.w = acc[i][3] * g + bw;
            *(float4*)&Cout[(size_t)m * ldc + n] = o;
        }
    }
}

// ---------------------------------------------------------------------------
// Window attention. One block = (window, head, batch*branch).
// 128 tokens per window (8x16 or 16x8), head dim 24, online softmax.
// q from x-qkv, k from y-qkv, v from x-qkv. Writes att (B,L,C) directly.
// ---------------------------------------------------------------------------
__global__ __launch_bounds__(128) void win_attn(
    const float* __restrict__ q, const float* __restrict__ k,
    const float* __restrict__ v, float* __restrict__ out)
{
    __shared__ float Ks[128][DD];
    __shared__ float Vs[128][DD];

    const int wid  = blockIdx.x;      // 0..127 window within image+branch
    const int head = blockIdx.y;      // 0..3
    const int z    = blockIdx.z;      // 0..15
    const int b  = z >> 1;
    const int br = z & 1;

    const int Hs  = br ? 16 : 8;
    const int Wsp = br ? 8 : 16;
    const int nWw = WW / Wsp;
    const int wy = wid / nWw, wx = wid % nWw;
    const int h0 = wy * Hs, w0 = wx * Wsp;
    const int cb = br * CHH + head * DD;
    const int tid = threadIdx.x;

    // cooperative K,V load
    for (int idx = tid; idx < 128 * DD; idx += 128) {
        int t = idx / DD, d = idx - t * DD;
        int hs = t / Wsp, ws = t - hs * Wsp;
        int l = (h0 + hs) * WW + (w0 + ws);
        size_t base = ((size_t)b * LL + l) * CC + cb + d;
        Ks[t][d] = k[base];
        Vs[t][d] = v[base];
    }
    __syncthreads();

    // own query row
    const int hs = tid / Wsp, ws = tid - hs * Wsp;
    const int l = (h0 + hs) * WW + (w0 + ws);
    const size_t qbase = ((size_t)b * LL + l) * CC + cb;

    float qreg[DD];
    #pragma unroll
    for (int d = 0; d < DD; d++) qreg[d] = q[qbase + d] * SCALE;

    float mrun = -1e30f, lsum = 0.f;
    float acc[DD];
    #pragma unroll
    for (int d = 0; d < DD; d++) acc[d] = 0.f;

    for (int j = 0; j < 128; j++) {
        float s = 0.f;
        #pragma unroll
        for (int d = 0; d < DD; d++) s += qreg[d] * Ks[j][d];
        if (s > mrun) {                       // rare after warm-up
            float corr = __expf(mrun - s);
            lsum *= corr;
            #pragma unroll
            for (int d = 0; d < DD; d++) acc[d] *= corr;
            mrun = s;
        }
        float p = __expf(s - mrun);
        lsum += p;
        #pragma unroll
        for (int d = 0; d < DD; d++) acc[d] += p * Vs[j][d];
    }

    float inv = 1.f / lsum;
    #pragma unroll
    for (int d = 0; d < DD; d++) out[qbase + d] = acc[d] * inv;
}

// ---------------------------------------------------------------------------
// Depthwise 3x3 conv (SAME) + bias + BN + exact GELU, channel-last layout.
// ---------------------------------------------------------------------------
__global__ __launch_bounds__(256) void dwconv_bn_gelu(
    const float* __restrict__ x, const float* __restrict__ wgt,
    const float* __restrict__ wb,
    const float* __restrict__ g1, const float* __restrict__ b1,
    const float* __restrict__ m1, const float* __restrict__ v1r,
    float* __restrict__ out)
{
    int idx = blockIdx.x * 256 + threadIdx.x;
    if (idx >= MM * CC) return;
    int c = idx % CC;
    int rem = idx / CC;
    int l = rem % LL;
    int b = rem / LL;
    int h = l >> 7, w = l & 127;

    float acc = 0.f;
    #pragma unroll
    for (int kh = 0; kh < 3; kh++) {
        int hh = h + kh - 1;
        if ((unsigned)hh >= (unsigned)HH) continue;
        #pragma unroll
        for (int kw = 0; kw < 3; kw++) {
            int ww = w + kw - 1;
            if ((unsigned)ww >= (unsigned)WW) continue;
            acc += x[((size_t)b * LL + hh * WW + ww) * CC + c] * wgt[c * 9 + kh * 3 + kw];
        }
    }
    acc += wb[c];
    float sc = g1[c] * rsqrtf(v1r[c] + EPSV);
    float t = (acc - m1[c]) * sc + b1[c];
    out[idx] = 0.5f * t * (1.f + erff(t * 0.70710678118654752f));
}

// ---------------------------------------------------------------------------
// Transpose si_w1 (96,192) -> (192,96) so the 1x1 conv runs through sgemm192.
// ---------------------------------------------------------------------------
__global__ void transpose_w1(const float* __restrict__ w1, float* __restrict__ w1t)
{
    int idx = blockIdx.x * 256 + threadIdx.x;
    if (idx >= 96 * 192) return;
    int j = idx / 192, c = idx - j * 192;
    w1t[c * 96 + j] = w1[idx];
}

// ---------------------------------------------------------------------------
// gate[m] = sigmoid( sum_j si_w2[j] * gelu(bn2(hid[m,j])) + si_b2 )
// One warp per pixel (hid already includes si_b1 via GEMM bias).
// ---------------------------------------------------------------------------
__global__ __launch_bounds__(128) void gate_kernel(
    const float* __restrict__ hid,
    const float* __restrict__ g2, const float* __restrict__ b2,
    const float* __restrict__ m2, const float* __restrict__ v2r,
    const float* __restrict__ w2, const float* __restrict__ sb2,
    float* __restrict__ gate)
{
    int m = blockIdx.x * 4 + (threadIdx.x >> 5);
    int lane = threadIdx.x & 31;
    float sum = 0.f;
    #pragma unroll
    for (int jj = 0; jj < 3; jj++) {
        int j = lane + jj * 32;
        float t = hid[(size_t)m * 96 + j];
        float sc = g2[j] * rsqrtf(v2r[j] + EPSV);
        t = (t - m2[j]) * sc + b2[j];
        t = 0.5f * t * (1.f + erff(t * 0.70710678118654752f));
        sum += t * w2[j];
    }
    #pragma unroll
    for (int o = 16; o; o >>= 1) sum += __shfl_xor_sync(0xffffffffu, sum, o);
    if (lane == 0) {
        float s = sum + sb2[0];
        gate[m] = 1.f / (1.f + __expf(-s));
    }
}

// ---------------------------------------------------------------------------
extern "C" void kernel_launch(void* const* d_in, const int* in_sizes, int n_in,
                              void* d_out, int out_size)
{
    const float* x     = (const float*)d_in[0];
    const float* y     = (const float*)d_in[1];
    const float* Wqkv  = (const float*)d_in[2];
    const float* bqkv  = (const float*)d_in[3];
    const float* dw_w  = (const float*)d_in[4];
    const float* dw_b  = (const float*)d_in[5];
    const float* bn1_g = (const float*)d_in[6];
    const float* bn1_b = (const float*)d_in[7];
    const float* bn1_m = (const float*)d_in[8];
    const float* bn1_v = (const float*)d_in[9];
    const float* si_w1 = (const float*)d_in[10];
    const float* si_b1 = (const float*)d_in[11];
    const float* bn2_g = (const float*)d_in[12];
    const float* bn2_b = (const float*)d_in[13];
    const float* bn2_m = (const float*)d_in[14];
    const float* bn2_v = (const float*)d_in[15];
    const float* si_w2 = (const float*)d_in[16];
    const float* si_b2 = (const float*)d_in[17];
    const float* projw = (const float*)d_in[18];
    const float* projb = (const float*)d_in[19];

    float* scratch = nullptr;
    cudaGetSymbolAddress((void**)&scratch, g_scratch);

    float* q1   = scratch + OFF_Q1;
    float* v1   = scratch + OFF_V1;
    float* k2   = scratch + OFF_K2;
    float* v2   = scratch + OFF_V2;
    float* att  = scratch + OFF_ATT;
    float* conv = scratch + OFF_CONV;
    float* hid  = scratch + OFF_HID;
    float* gate = scratch + OFF_GATE;
    float* w1t  = scratch + OFF_W1T;

    dim3 gemmGrid(MM / 64, 3);

    // qkv projections (only the 4 needed slices)
    sgemm192<<<gemmGrid, 256>>>(x, CC, Wqkv + 0,       3 * CC, bqkv + 0,       nullptr, q1, CC, CC);
    sgemm192<<<gemmGrid, 256>>>(x, CC, Wqkv + 2 * CC,  3 * CC, bqkv + 2 * CC,  nullptr, v1, CC, CC);
    sgemm192<<<gemmGrid, 256>>>(y, CC, Wqkv + CC,      3 * CC, bqkv + CC,      nullptr, k2, CC, CC);
    sgemm192<<<gemmGrid, 256>>>(y, CC, Wqkv + 2 * CC,  3 * CC, bqkv + 2 * CC,  nullptr, v2, CC, CC);

    // window attention (both branches, all heads)
    win_attn<<<dim3(128, NHH, BB * 2), 128>>>(q1, k2, v1, att);

    // conv gating path on v2
    dwconv_bn_gelu<<<(MM * CC + 255) / 256, 256>>>(v2, dw_w, dw_b,
                                                   bn1_g, bn1_b, bn1_m, bn1_v, conv);
    transpose_w1<<<(96 * 192 + 255) / 256, 256>>>(si_w1, w1t);
    sgemm192<<<dim3(MM / 64, 2), 256>>>(conv, CC, w1t, 96, si_b1, nullptr, hid, 96, 96);
    gate_kernel<<<MM / 4, 128>>>(hid, bn2_g, bn2_b, bn2_m, bn2_v, si_w2, si_b2, gate);

    // final projection with fused per-row sigmoid gate
    sgemm192<<<gemmGrid, 256>>>(att, CC, projw, CC, projb, gate, (float*)d_out, CC, CC);
}

// round 4
// speedup vs baseline: 1.1244x; 1.1237x over previous
#include <cuda_runtime.h>
#include <math.h>

// Problem constants (fixed by the bench: B=8, H=W=128, C=192, split=(8,16), heads=8)
#define BB   8
#define HH   128
#define WW   128
#define CC   192
#define LL   (HH * WW)          // 16384
#define MM   (BB * LL)          // 131072 rows
#define CHH  96                 // C/2 per branch
#define NHH  4                  // heads per branch
#define DD   24                 // head dim
#define EPSV 1e-5f
#define SCALE 0.20412414523193154f   // 24^-0.5

// ---------------------------------------------------------------------------
// Scratch arena (no allocations allowed). Offsets in floats.
// ---------------------------------------------------------------------------
#define OFF_Q1   ((size_t)0)
#define OFF_V1   (OFF_Q1  + (size_t)MM * CC)
#define OFF_K2   (OFF_V1  + (size_t)MM * CC)
#define OFF_V2   (OFF_K2  + (size_t)MM * CC)
#define OFF_ATT  (OFF_V2  + (size_t)MM * CC)
#define OFF_CONV (OFF_ATT + (size_t)MM * CC)
#define OFF_HID  (OFF_CONV + (size_t)MM * CC)
#define OFF_GATE (OFF_HID + (size_t)MM * 96)
#define OFF_W1T  (OFF_GATE + (size_t)MM)
#define SCRATCH_FLOATS (OFF_W1T + (size_t)192 * 96)

__device__ float g_scratch[SCRATCH_FLOATS];

// ---------------------------------------------------------------------------
// SGEMM, K fixed at 192. C[m,n] = gate[m] * (A[m,:] @ B[:,n]) + bias[n]
// 128x64 block tile, BK=16, 256 threads, 8x4 micro-tile.
// A fragment: 2x LDS.128 (warp-broadcast, conflict-free, k-major As).
// B fragment: 1x LDS.128 (2 conflict-free wavefronts).
// -> 3 LDS per 32 FFMA per thread (was 5 LDS per 16): FMA-bound, not L1-bound.
// ---------------------------------------------------------------------------
__global__ __launch_bounds__(256) void sgemm192(
    const float* __restrict__ A, int lda,
    const float* __restrict__ Bm, int ldb,
    const float* __restrict__ bias,
    const float* __restrict__ gate,
    float* __restrict__ Cout, int ldc, int N)
{
    __shared__ float As[16][128];   // k-major
    __shared__ float Bs[16][64];

    const int bm = blockIdx.x * 128;
    const int bn = blockIdx.y * 64;
    const int tid = threadIdx.x;

    // A tile load mapping: 128 rows x 16 cols, 2 float4 per thread
    const int arow = tid >> 1;            // 0..127
    const int acg  = (tid & 1) << 3;      // 0 or 8
    // B tile load mapping: 16 rows x 64 cols, 1 float4 per thread
    const int brow = tid >> 4;            // 0..15
    const int bcol = (tid & 15) << 2;     // 0..60

    // compute mapping
    const int tx = tid & 15;              // n: 4 cols
    const int ty = tid >> 4;              // m: 8 rows

    float acc[8][4] = {};

    const float* Aptr = A + (size_t)(bm + arow) * lda + acg;
    const float* Bptr = Bm + bn + bcol;
    const bool bvalid = (bn + bcol) < N;

    for (int k0 = 0; k0 < 192; k0 += 16) {
        float4 a0 = *(const float4*)(Aptr + k0);
        float4 a1 = *(const float4*)(Aptr + k0 + 4);
        float4 bv = bvalid ? *(const float4*)(Bptr + (size_t)(k0 + brow) * ldb)
                           : make_float4(0.f, 0.f, 0.f, 0.f);

        As[acg + 0][arow] = a0.x;
        As[acg + 1][arow] = a0.y;
        As[acg + 2][arow] = a0.z;
        As[acg + 3][arow] = a0.w;
        As[acg + 4][arow] = a1.x;
        As[acg + 5][arow] = a1.y;
        As[acg + 6][arow] = a1.z;
        As[acg + 7][arow] = a1.w;
        *(float4*)&Bs[brow][bcol] = bv;

        __syncthreads();

        #pragma unroll
        for (int k = 0; k < 16; k++) {
            float4 af0 = *(const float4*)&As[k][ty * 8];
            float4 af1 = *(const float4*)&As[k][ty * 8 + 4];
            float4 bf  = *(const float4*)&Bs[k][tx * 4];
            float a[8] = {af0.x, af0.y, af0.z, af0.w, af1.x, af1.y, af1.z, af1.w};
            #pragma unroll
            for (int i = 0; i < 8; i++) {
                acc[i][0] += a[i] * bf.x;
                acc[i][1] += a[i] * bf.y;
                acc[i][2] += a[i] * bf.z;
                acc[i][3] += a[i] * bf.w;
            }
        }
        __syncthreads();
    }

    const int n = bn + tx * 4;
    if (n < N) {
        float bx = bias ? bias[n + 0] : 0.f;
        float by = bias ? bias[n + 1] : 0.f;
        float bz = bias ? bias[n + 2] : 0.f;
        float bw = bias ? bias[n + 3] : 0.f;
        #pragma unroll
        for (int i = 0; i < 8; i++) {
            int m = bm + ty * 8 + i;
            float g = gate ? gate[m] : 1.0f;
            float4 o;
            o.x = acc[i][0] * g + bx;
            o.y = acc[i][1] * g + by;
            o.z = acc[i][2] * g + bz;
            o.w = acc[i][3] * g + bw;
            *(float4*)&Cout[(size_t)m * ldc + n] = o;
        }
    }
}

// ---------------------------------------------------------------------------
// Window attention. One block = (window, head, batch*branch).
// 128 tokens per window (8x16 or 16x8), head dim 24, online softmax.
// ---------------------------------------------------------------------------
__global__ __launch_bounds__(128) void win_attn(
    const float* __restrict__ q, const float* __restrict__ k,
    const float* __restrict__ v, float* __restrict__ out)
{
    __shared__ float Ks[128][DD];
    __shared__ float Vs[128][DD];

    const int wid  = blockIdx.x;      // 0..127 window within image+branch
    const int head = blockIdx.y;      // 0..3
    const int z    = blockIdx.z;      // 0..15
    const int b  = z >> 1;
    const int br = z & 1;

    const int Hs  = br ? 16 : 8;
    const int Wsp = br ? 8 : 16;
    const int nWw = WW / Wsp;
    const int wy = wid / nWw, wx = wid % nWw;
    const int h0 = wy * Hs, w0 = wx * Wsp;
    const int cb = br * CHH + head * DD;
    const int tid = threadIdx.x;

    // cooperative K,V load
    for (int idx = tid; idx < 128 * DD; idx += 128) {
        int t = idx / DD, d = idx - t * DD;
        int hs = t / Wsp, ws = t - hs * Wsp;
        int l = (h0 + hs) * WW + (w0 + ws);
        size_t base = ((size_t)b * LL + l) * CC + cb + d;
        Ks[t][d] = k[base];
        Vs[t][d] = v[base];
    }
    __syncthreads();

    // own query row
    const int hs = tid / Wsp, ws = tid - hs * Wsp;
    const int l = (h0 + hs) * WW + (w0 + ws);
    const size_t qbase = ((size_t)b * LL + l) * CC + cb;

    float qreg[DD];
    #pragma unroll
    for (int d = 0; d < DD; d++) qreg[d] = q[qbase + d] * SCALE;

    float mrun = -1e30f, lsum = 0.f;
    float acc[DD];
    #pragma unroll
    for (int d = 0; d < DD; d++) acc[d] = 0.f;

    for (int j = 0; j < 128; j++) {
        float s = 0.f;
        #pragma unroll
        for (int d = 0; d < DD; d++) s += qreg[d] * Ks[j][d];
        if (s > mrun) {                       // rare after warm-up
            float corr = __expf(mrun - s);
            lsum *= corr;
            #pragma unroll
            for (int d = 0; d < DD; d++) acc[d] *= corr;
            mrun = s;
        }
        float p = __expf(s - mrun);
        lsum += p;
        #pragma unroll
        for (int d = 0; d < DD; d++) acc[d] += p * Vs[j][d];
    }

    float inv = 1.f / lsum;
    #pragma unroll
    for (int d = 0; d < DD; d++) out[qbase + d] = acc[d] * inv;
}

// ---------------------------------------------------------------------------
// Depthwise 3x3 conv (SAME) + bias + BN + exact GELU, channel-last layout.
// ---------------------------------------------------------------------------
__global__ __launch_bounds__(256) void dwconv_bn_gelu(
    const float* __restrict__ x, const float* __restrict__ wgt,
    const float* __restrict__ wb,
    const float* __restrict__ g1, const float* __restrict__ b1,
    const float* __restrict__ m1, const float* __restrict__ v1r,
    float* __restrict__ out)
{
    int idx = blockIdx.x * 256 + threadIdx.x;
    if (idx >= MM * CC) return;
    int c = idx % CC;
    int rem = idx / CC;
    int l = rem % LL;
    int b = rem / LL;
    int h = l >> 7, w = l & 127;

    float acc = 0.f;
    #pragma unroll
    for (int kh = 0; kh < 3; kh++) {
        int hh = h + kh - 1;
        if ((unsigned)hh >= (unsigned)HH) continue;
        #pragma unroll
        for (int kw = 0; kw < 3; kw++) {
            int ww = w + kw - 1;
            if ((unsigned)ww >= (unsigned)WW) continue;
            acc += x[((size_t)b * LL + hh * WW + ww) * CC + c] * wgt[c * 9 + kh * 3 + kw];
        }
    }
    acc += wb[c];
    float sc = g1[c] * rsqrtf(v1r[c] + EPSV);
    float t = (acc - m1[c]) * sc + b1[c];
    out[idx] = 0.5f * t * (1.f + erff(t * 0.70710678118654752f));
}

// ---------------------------------------------------------------------------
// Transpose si_w1 (96,192) -> (192,96) so the 1x1 conv runs through sgemm192.
// ---------------------------------------------------------------------------
__global__ void transpose_w1(const float* __restrict__ w1, float* __restrict__ w1t)
{
    int idx = blockIdx.x * 256 + threadIdx.x;
    if (idx >= 96 * 192) return;
    int j = idx / 192, c = idx - j * 192;
    w1t[c * 96 + j] = w1[idx];
}

// ---------------------------------------------------------------------------
// gate[m] = sigmoid( sum_j si_w2[j] * gelu(bn2(hid[m,j])) + si_b2 )
// ---------------------------------------------------------------------------
__global__ __launch_bounds__(128) void gate_kernel(
    const float* __restrict__ hid,
    const float* __restrict__ g2, const float* __restrict__ b2,
    const float* __restrict__ m2, const float* __restrict__ v2r,
    const float* __restrict__ w2, const float* __restrict__ sb2,
    float* __restrict__ gate)
{
    int m = blockIdx.x * 4 + (threadIdx.x >> 5);
    int lane = threadIdx.x & 31;
    float sum = 0.f;
    #pragma unroll
    for (int jj = 0; jj < 3; jj++) {
        int j = lane + jj * 32;
        float t = hid[(size_t)m * 96 + j];
        float sc = g2[j] * rsqrtf(v2r[j] + EPSV);
        t = (t - m2[j]) * sc + b2[j];
        t = 0.5f * t * (1.f + erff(t * 0.70710678118654752f));
        sum += t * w2[j];
    }
    #pragma unroll
    for (int o = 16; o; o >>= 1) sum += __shfl_xor_sync(0xffffffffu, sum, o);
    if (lane == 0) {
        float s = sum + sb2[0];
        gate[m] = 1.f / (1.f + __expf(-s));
    }
}

// ---------------------------------------------------------------------------
extern "C" void kernel_launch(void* const* d_in, const int* in_sizes, int n_in,
                              void* d_out, int out_size)
{
    const float* x     = (const float*)d_in[0];
    const float* y     = (const float*)d_in[1];
    const float* Wqkv  = (const float*)d_in[2];
    const float* bqkv  = (const float*)d_in[3];
    const float* dw_w  = (const float*)d_in[4];
    const float* dw_b  = (const float*)d_in[5];
    const float* bn1_g = (const float*)d_in[6];
    const float* bn1_b = (const float*)d_in[7];
    const float* bn1_m = (const float*)d_in[8];
    const float* bn1_v = (const float*)d_in[9];
    const float* si_w1 = (const float*)d_in[10];
    const float* si_b1 = (const float*)d_in[11];
    const float* bn2_g = (const float*)d_in[12];
    const float* bn2_b = (const float*)d_in[13];
    const float* bn2_m = (const float*)d_in[14];
    const float* bn2_v = (const float*)d_in[15];
    const float* si_w2 = (const float*)d_in[16];
    const float* si_b2 = (const float*)d_in[17];
    const float* projw = (const float*)d_in[18];
    const float* projb = (const float*)d_in[19];

    float* scratch = nullptr;
    cudaGetSymbolAddress((void**)&scratch, g_scratch);

    float* q1   = scratch + OFF_Q1;
    float* v1   = scratch + OFF_V1;
    float* k2   = scratch + OFF_K2;
    float* v2   = scratch + OFF_V2;
    float* att  = scratch + OFF_ATT;
    float* conv = scratch + OFF_CONV;
    float* hid  = scratch + OFF_HID;
    float* gate = scratch + OFF_GATE;
    float* w1t  = scratch + OFF_W1T;

    dim3 gemmGrid(MM / 128, 3);

    // qkv projections (only the 4 needed slices)
    sgemm192<<<gemmGrid, 256>>>(x, CC, Wqkv + 0,       3 * CC, bqkv + 0,       nullptr, q1, CC, CC);
    sgemm192<<<gemmGrid, 256>>>(x, CC, Wqkv + 2 * CC,  3 * CC, bqkv + 2 * CC,  nullptr, v1, CC, CC);
    sgemm192<<<gemmGrid, 256>>>(y, CC, Wqkv + CC,      3 * CC, bqkv + CC,      nullptr, k2, CC, CC);
    sgemm192<<<gemmGrid, 256>>>(y, CC, Wqkv + 2 * CC,  3 * CC, bqkv + 2 * CC,  nullptr, v2, CC, CC);

    // window attention (both branches, all heads)
    win_attn<<<dim3(128, NHH, BB * 2), 128>>>(q1, k2, v1, att);

    // conv gating path on v2
    dwconv_bn_gelu<<<(MM * CC + 255) / 256, 256>>>(v2, dw_w, dw_b,
                                                   bn1_g, bn1_b, bn1_m, bn1_v, conv);
    transpose_w1<<<(96 * 192 + 255) / 256, 256>>>(si_w1, w1t);
    sgemm192<<<dim3(MM / 128, 2), 256>>>(conv, CC, w1t, 96, si_b1, nullptr, hid, 96, 96);
    gate_kernel<<<MM / 4, 128>>>(hid, bn2_g, bn2_b, bn2_m, bn2_v, si_w2, si_b2, gate);

    // final projection with fused per-row sigmoid gate
    sgemm192<<<gemmGrid, 256>>>(att, CC, projw, CC, projb, gate, (float*)d_out, CC, CC);
}

// round 5
// speedup vs baseline: 1.1254x; 1.0009x over previous
#include <cuda_runtime.h>
#include <math.h>

// Problem constants (fixed by the bench: B=8, H=W=128, C=192, split=(8,16), heads=8)
#define BB   8
#define HH   128
#define WW   128
#define CC   192
#define LL   (HH * WW)          // 16384
#define MM   (BB * LL)          // 131072 rows
#define CHH  96                 // C/2 per branch
#define NHH  4                  // heads per branch
#define DD   24                 // head dim
#define EPSV 1e-5f
#define SCALE 0.20412414523193154f   // 24^-0.5

// ---------------------------------------------------------------------------
// Scratch arena (no allocations allowed). Offsets in floats.
// ---------------------------------------------------------------------------
#define OFF_Q1   ((size_t)0)
#define OFF_V1   (OFF_Q1  + (size_t)MM * CC)
#define OFF_K2   (OFF_V1  + (size_t)MM * CC)
#define OFF_V2   (OFF_K2  + (size_t)MM * CC)
#define OFF_ATT  (OFF_V2  + (size_t)MM * CC)
#define OFF_CONV (OFF_ATT + (size_t)MM * CC)
#define OFF_HID  (OFF_CONV + (size_t)MM * CC)
#define OFF_GATE (OFF_HID + (size_t)MM * 96)
#define OFF_W1T  (OFF_GATE + (size_t)MM)
#define SCRATCH_FLOATS (OFF_W1T + (size_t)192 * 96)

__device__ float g_scratch[SCRATCH_FLOATS];

// ---------------------------------------------------------------------------
// SGEMM, K fixed at 192. C[m,n] = gate[m] * (A[m,:] @ B[:,n]) + bias[n]
// 128x64 block tile, BK=16, 256 threads, 8x4 micro-tile.
// A fragment: 2x LDS.128 (warp-broadcast, conflict-free, k-major As).
// B fragment: 1x LDS.128 (2 conflict-free wavefronts).
// -> 3 LDS per 32 FFMA per thread (was 5 LDS per 16): FMA-bound, not L1-bound.
// ---------------------------------------------------------------------------
__global__ __launch_bounds__(256) void sgemm192(
    const float* __restrict__ A, int lda,
    const float* __restrict__ Bm, int ldb,
    const float* __restrict__ bias,
    const float* __restrict__ gate,
    float* __restrict__ Cout, int ldc, int N)
{
    __shared__ float As[16][128];   // k-major
    __shared__ float Bs[16][64];

    const int bm = blockIdx.x * 128;
    const int bn = blockIdx.y * 64;
    const int tid = threadIdx.x;

    // A tile load mapping: 128 rows x 16 cols, 2 float4 per thread
    const int arow = tid >> 1;            // 0..127
    const int acg  = (tid & 1) << 3;      // 0 or 8
    // B tile load mapping: 16 rows x 64 cols, 1 float4 per thread
    const int brow = tid >> 4;            // 0..15
    const int bcol = (tid & 15) << 2;     // 0..60

    // compute mapping
    const int tx = tid & 15;              // n: 4 cols
    const int ty = tid >> 4;              // m: 8 rows

    float acc[8][4] = {};

    const float* Aptr = A + (size_t)(bm + arow) * lda + acg;
    const float* Bptr = Bm + bn + bcol;
    const bool bvalid = (bn + bcol) < N;

    for (int k0 = 0; k0 < 192; k0 += 16) {
        float4 a0 = *(const float4*)(Aptr + k0);
        float4 a1 = *(const float4*)(Aptr + k0 + 4);
        float4 bv = bvalid ? *(const float4*)(Bptr + (size_t)(k0 + brow) * ldb)
                           : make_float4(0.f, 0.f, 0.f, 0.f);

        As[acg + 0][arow] = a0.x;
        As[acg + 1][arow] = a0.y;
        As[acg + 2][arow] = a0.z;
        As[acg + 3][arow] = a0.w;
        As[acg + 4][arow] = a1.x;
        As[acg + 5][arow] = a1.y;
        As[acg + 6][arow] = a1.z;
        As[acg + 7][arow] = a1.w;
        *(float4*)&Bs[brow][bcol] = bv;

        __syncthreads();

        #pragma unroll
        for (int k = 0; k < 16; k++) {
            float4 af0 = *(const float4*)&As[k][ty * 8];
            float4 af1 = *(const float4*)&As[k][ty * 8 + 4];
            float4 bf  = *(const float4*)&Bs[k][tx * 4];
            float a[8] = {af0.x, af0.y, af0.z, af0.w, af1.x, af1.y, af1.z, af1.w};
            #pragma unroll
            for (int i = 0; i < 8; i++) {
                acc[i][0] += a[i] * bf.x;
                acc[i][1] += a[i] * bf.y;
                acc[i][2] += a[i] * bf.z;
                acc[i][3] += a[i] * bf.w;
            }
        }
        __syncthreads();
    }

    const int n = bn + tx * 4;
    if (n < N) {
        float bx = bias ? bias[n + 0] : 0.f;
        float by = bias ? bias[n + 1] : 0.f;
        float bz = bias ? bias[n + 2] : 0.f;
        float bw = bias ? bias[n + 3] : 0.f;
        #pragma unroll
        for (int i = 0; i < 8; i++) {
            int m = bm + ty * 8 + i;
            float g = gate ? gate[m] : 1.0f;
            float4 o;
            o.x = acc[i][0] * g + bx;
            o.y = acc[i][1] * g + by;
            o.z = acc[i][2] * g + bz;
            o.w = acc[i][3] * g + bw;
            *(float4*)&Cout[(size_t)m * ldc + n] = o;
        }
    }
}

// ---------------------------------------------------------------------------
// Window attention. One block = (window, head, batch*branch).
// 128 tokens per window (8x16 or 16x8), head dim 24, online softmax.
// ---------------------------------------------------------------------------
__global__ __launch_bounds__(128) void win_attn(
    const float* __restrict__ q, const float* __restrict__ k,
    const float* __restrict__ v, float* __restrict__ out)
{
    __shared__ float Ks[128][DD];
    __shared__ float Vs[128][DD];

    const int wid  = blockIdx.x;      // 0..127 window within image+branch
    const int head = blockIdx.y;      // 0..3
    const int z    = blockIdx.z;      // 0..15
    const int b  = z >> 1;
    const int br = z & 1;

    const int Hs  = br ? 16 : 8;
    const int Wsp = br ? 8 : 16;
    const int nWw = WW / Wsp;
    const int wy = wid / nWw, wx = wid % nWw;
    const int h0 = wy * Hs, w0 = wx * Wsp;
    const int cb = br * CHH + head * DD;
    const int tid = threadIdx.x;

    // cooperative K,V load
    for (int idx = tid; idx < 128 * DD; idx += 128) {
        int t = idx / DD, d = idx - t * DD;
        int hs = t / Wsp, ws = t - hs * Wsp;
        int l = (h0 + hs) * WW + (w0 + ws);
        size_t base = ((size_t)b * LL + l) * CC + cb + d;
        Ks[t][d] = k[base];
        Vs[t][d] = v[base];
    }
    __syncthreads();

    // own query row
    const int hs = tid / Wsp, ws = tid - hs * Wsp;
    const int l = (h0 + hs) * WW + (w0 + ws);
    const size_t qbase = ((size_t)b * LL + l) * CC + cb;

    float qreg[DD];
    #pragma unroll
    for (int d = 0; d < DD; d++) qreg[d] = q[qbase + d] * SCALE;

    float mrun = -1e30f, lsum = 0.f;
    float acc[DD];
    #pragma unroll
    for (int d = 0; d < DD; d++) acc[d] = 0.f;

    for (int j = 0; j < 128; j++) {
        float s = 0.f;
        #pragma unroll
        for (int d = 0; d < DD; d++) s += qreg[d] * Ks[j][d];
        if (s > mrun) {                       // rare after warm-up
            float corr = __expf(mrun - s);
            lsum *= corr;
            #pragma unroll
            for (int d = 0; d < DD; d++) acc[d] *= corr;
            mrun = s;
        }
        float p = __expf(s - mrun);
        lsum += p;
        #pragma unroll
        for (int d = 0; d < DD; d++) acc[d] += p * Vs[j][d];
    }

    float inv = 1.f / lsum;
    #pragma unroll
    for (int d = 0; d < DD; d++) out[qbase + d] = acc[d] * inv;
}

// ---------------------------------------------------------------------------
// Depthwise 3x3 conv (SAME) + bias + BN + exact GELU, channel-last layout.
// ---------------------------------------------------------------------------
__global__ __launch_bounds__(256) void dwconv_bn_gelu(
    const float* __restrict__ x, const float* __restrict__ wgt,
    const float* __restrict__ wb,
    const float* __restrict__ g1, const float* __restrict__ b1,
    const float* __restrict__ m1, const float* __restrict__ v1r,
    float* __restrict__ out)
{
    int idx = blockIdx.x * 256 + threadIdx.x;
    if (idx >= MM * CC) return;
    int c = idx % CC;
    int rem = idx / CC;
    int l = rem % LL;
    int b = rem / LL;
    int h = l >> 7, w = l & 127;

    float acc = 0.f;
    #pragma unroll
    for (int kh = 0; kh < 3; kh++) {
        int hh = h + kh - 1;
        if ((unsigned)hh >= (unsigned)HH) continue;
        #pragma unroll
        for (int kw = 0; kw < 3; kw++) {
            int ww = w + kw - 1;
            if ((unsigned)ww >= (unsigned)WW) continue;
            acc += x[((size_t)b * LL + hh * WW + ww) * CC + c] * wgt[c * 9 + kh * 3 + kw];
        }
    }
    acc += wb[c];
    float sc = g1[c] * rsqrtf(v1r[c] + EPSV);
    float t = (acc - m1[c]) * sc + b1[c];
    out[idx] = 0.5f * t * (1.f + erff(t * 0.70710678118654752f));
}

// ---------------------------------------------------------------------------
// Transpose si_w1 (96,192) -> (192,96) so the 1x1 conv runs through sgemm192.
// ---------------------------------------------------------------------------
__global__ void transpose_w1(const float* __restrict__ w1, float* __restrict__ w1t)
{
    int idx = blockIdx.x * 256 + threadIdx.x;
    if (idx >= 96 * 192) return;
    int j = idx / 192, c = idx - j * 192;
    w1t[c * 96 + j] = w1[idx];
}

// ---------------------------------------------------------------------------
// gate[m] = sigmoid( sum_j si_w2[j] * gelu(bn2(hid[m,j])) + si_b2 )
// ---------------------------------------------------------------------------
__global__ __launch_bounds__(128) void gate_kernel(
    const float* __restrict__ hid,
    const float* __restrict__ g2, const float* __restrict__ b2,
    const float* __restrict__ m2, const float* __restrict__ v2r,
    const float* __restrict__ w2, const float* __restrict__ sb2,
    float* __restrict__ gate)
{
    int m = blockIdx.x * 4 + (threadIdx.x >> 5);
    int lane = threadIdx.x & 31;
    float sum = 0.f;
    #pragma unroll
    for (int jj = 0; jj < 3; jj++) {
        int j = lane + jj * 32;
        float t = hid[(size_t)m * 96 + j];
        float sc = g2[j] * rsqrtf(v2r[j] + EPSV);
        t = (t - m2[j]) * sc + b2[j];
        t = 0.5f * t * (1.f + erff(t * 0.70710678118654752f));
        sum += t * w2[j];
    }
    #pragma unroll
    for (int o = 16; o; o >>= 1) sum += __shfl_xor_sync(0xffffffffu, sum, o);
    if (lane == 0) {
        float s = sum + sb2[0];
        gate[m] = 1.f / (1.f + __expf(-s));
    }
}

// ---------------------------------------------------------------------------
extern "C" void kernel_launch(void* const* d_in, const int* in_sizes, int n_in,
                              void* d_out, int out_size)
{
    const float* x     = (const float*)d_in[0];
    const float* y     = (const float*)d_in[1];
    const float* Wqkv  = (const float*)d_in[2];
    const float* bqkv  = (const float*)d_in[3];
    const float* dw_w  = (const float*)d_in[4];
    const float* dw_b  = (const float*)d_in[5];
    const float* bn1_g = (const float*)d_in[6];
    const float* bn1_b = (const float*)d_in[7];
    const float* bn1_m = (const float*)d_in[8];
    const float* bn1_v = (const float*)d_in[9];
    const float* si_w1 = (const float*)d_in[10];
    const float* si_b1 = (const float*)d_in[11];
    const float* bn2_g = (const float*)d_in[12];
    const float* bn2_b = (const float*)d_in[13];
    const float* bn2_m = (const float*)d_in[14];
    const float* bn2_v = (const float*)d_in[15];
    const float* si_w2 = (const float*)d_in[16];
    const float* si_b2 = (const float*)d_in[17];
    const float* projw = (const float*)d_in[18];
    const float* projb = (const float*)d_in[19];

    float* scratch = nullptr;
    cudaGetSymbolAddress((void**)&scratch, g_scratch);

    float* q1   = scratch + OFF_Q1;
    float* v1   = scratch + OFF_V1;
    float* k2   = scratch + OFF_K2;
    float* v2   = scratch + OFF_V2;
    float* att  = scratch + OFF_ATT;
    float* conv = scratch + OFF_CONV;
    float* hid  = scratch + OFF_HID;
    float* gate = scratch + OFF_GATE;
    float* w1t  = scratch + OFF_W1T;

    dim3 gemmGrid(MM / 128, 3);

    // qkv projections (only the 4 needed slices)
    sgemm192<<<gemmGrid, 256>>>(x, CC, Wqkv + 0,       3 * CC, bqkv + 0,       nullptr, q1, CC, CC);
    sgemm192<<<gemmGrid, 256>>>(x, CC, Wqkv + 2 * CC,  3 * CC, bqkv + 2 * CC,  nullptr, v1, CC, CC);
    sgemm192<<<gemmGrid, 256>>>(y, CC, Wqkv + CC,      3 * CC, bqkv + CC,      nullptr, k2, CC, CC);
    sgemm192<<<gemmGrid, 256>>>(y, CC, Wqkv + 2 * CC,  3 * CC, bqkv + 2 * CC,  nullptr, v2, CC, CC);

    // window attention (both branches, all heads)
    win_attn<<<dim3(128, NHH, BB * 2), 128>>>(q1, k2, v1, att);

    // conv gating path on v2
    dwconv_bn_gelu<<<(MM * CC + 255) / 256, 256>>>(v2, dw_w, dw_b,
                                                   bn1_g, bn1_b, bn1_m, bn1_v, conv);
    transpose_w1<<<(96 * 192 + 255) / 256, 256>>>(si_w1, w1t);
    sgemm192<<<dim3(MM / 128, 2), 256>>>(conv, CC, w1t, 96, si_b1, nullptr, hid, 96, 96);
    gate_kernel<<<MM / 4, 128>>>(hid, bn2_g, bn2_b, bn2_m, bn2_v, si_w2, si_b2, gate);

    // final projection with fused per-row sigmoid gate
    sgemm192<<<gemmGrid, 256>>>(att, CC, projw, CC, projb, gate, (float*)d_out, CC, CC);
}

// round 6
// speedup vs baseline: 1.5614x; 1.3874x over previous
#include <cuda_runtime.h>
#include <math.h>
#include <stdint.h>

// Problem constants (fixed by the bench: B=8, H=W=128, C=192, split=(8,16), heads=8)
#define BB   8
#define HH   128
#define WW   128
#define CC   192
#define LL   (HH * WW)          // 16384
#define MM   (BB * LL)          // 131072 rows
#define CHH  96                 // C/2 per branch
#define NHH  4                  // heads per branch
#define DD   24                 // head dim
#define EPSV 1e-5f
#define SCALE 0.20412414523193154f   // 24^-0.5

// ---------------------------------------------------------------------------
// Scratch arena (no allocations allowed). Offsets in floats.
// ---------------------------------------------------------------------------
#define OFF_Q1   ((size_t)0)
#define OFF_V1   (OFF_Q1  + (size_t)MM * CC)
#define OFF_K2   (OFF_V1  + (size_t)MM * CC)
#define OFF_V2   (OFF_K2  + (size_t)MM * CC)
#define OFF_ATT  (OFF_V2  + (size_t)MM * CC)
#define OFF_CONV (OFF_ATT + (size_t)MM * CC)
#define OFF_HID  (OFF_CONV + (size_t)MM * CC)
#define OFF_GATE (OFF_HID + (size_t)MM * 96)
#define OFF_W1T  (OFF_GATE + (size_t)MM)
#define SCRATCH_FLOATS (OFF_W1T + (size_t)192 * 96)

__device__ float g_scratch[SCRATCH_FLOATS];

__device__ __forceinline__ uint32_t f2tf32(float f) {
    uint32_t u;
    asm("cvt.rna.tf32.f32 %0, %1;" : "=r"(u) : "f"(f));
    return u;
}

// ---------------------------------------------------------------------------
// TF32 tensor-core GEMM, K fixed at 192.
//   C[m,n] = gate[m] * (A[m,:] @ B[:,n]) + bias[n]
// Block tile 128x64, BK=16, 256 threads = 8 warps (4 in M x 2 in N).
// Warp tile 32x32 = 2x4 mma.m16n8k8 tiles. fp32 accumulate; inputs rounded
// to tf32 once at the smem fill.
// Smem pads chosen so both fragment-load patterns are bank-conflict-free:
//   As[128][20]: addr g*20+t mod 32 -> 32 distinct banks
//   Bs[16][72] : addr t*8 +g mod 32 -> 32 distinct banks
// ---------------------------------------------------------------------------
__global__ __launch_bounds__(256) void mma_gemm192(
    const float* __restrict__ A, int lda,
    const float* __restrict__ Bm, int ldb,
    const float* __restrict__ bias,
    const float* __restrict__ gate,
    float* __restrict__ Cout, int ldc, int N)
{
    __shared__ uint32_t As[128][20];
    __shared__ uint32_t Bs[16][72];

    const int tid  = threadIdx.x;
    const int warp = tid >> 5;
    const int lane = tid & 31;
    const int g = lane >> 2;          // 0..7
    const int t = lane & 3;           // 0..3

    const int warpM = warp & 3;       // 0..3 -> 32-row slab
    const int warpN = warp >> 2;      // 0..1 -> 32-col slab
    const int bm = blockIdx.x * 128;
    const int bn = blockIdx.y * 64;

    // gmem->smem mappings
    const int arow = tid >> 1;            // 0..127
    const int acol = (tid & 1) << 3;      // 0 or 8
    const int brow = tid >> 4;            // 0..15
    const int bcol = (tid & 15) << 2;     // 0..60

    const float* Aptr = A + (size_t)(bm + arow) * lda + acol;
    const float* Bptr = Bm + (size_t)brow * ldb + bn + bcol;
    const bool bval = (bn + bcol) < N;

    float acc[2][4][4];
    #pragma unroll
    for (int i = 0; i < 2; i++)
        #pragma unroll
        for (int j = 0; j < 4; j++)
            #pragma unroll
            for (int r = 0; r < 4; r++) acc[i][j][r] = 0.f;

    for (int k0 = 0; k0 < 192; k0 += 16) {
        float4 a0 = *(const float4*)(Aptr + k0);
        float4 a1 = *(const float4*)(Aptr + k0 + 4);
        float4 bv = bval ? *(const float4*)(Bptr + (size_t)k0 * ldb)
                         : make_float4(0.f, 0.f, 0.f, 0.f);

        As[arow][acol + 0] = f2tf32(a0.x);
        As[arow][acol + 1] = f2tf32(a0.y);
        As[arow][acol + 2] = f2tf32(a0.z);
        As[arow][acol + 3] = f2tf32(a0.w);
        As[arow][acol + 4] = f2tf32(a1.x);
        As[arow][acol + 5] = f2tf32(a1.y);
        As[arow][acol + 6] = f2tf32(a1.z);
        As[arow][acol + 7] = f2tf32(a1.w);
        Bs[brow][bcol + 0] = f2tf32(bv.x);
        Bs[brow][bcol + 1] = f2tf32(bv.y);
        Bs[brow][bcol + 2] = f2tf32(bv.z);
        Bs[brow][bcol + 3] = f2tf32(bv.w);

        __syncthreads();

        #pragma unroll
        for (int kk = 0; kk < 16; kk += 8) {
            uint32_t afr[2][4];
            #pragma unroll
            for (int mi = 0; mi < 2; mi++) {
                int row = warpM * 32 + mi * 16 + g;
                afr[mi][0] = As[row    ][kk + t    ];
                afr[mi][1] = As[row + 8][kk + t    ];
                afr[mi][2] = As[row    ][kk + t + 4];
                afr[mi][3] = As[row + 8][kk + t + 4];
            }
            uint32_t bfr[4][2];
            #pragma unroll
            for (int ni = 0; ni < 4; ni++) {
                int col = warpN * 32 + ni * 8 + g;
                bfr[ni][0] = Bs[kk + t    ][col];
                bfr[ni][1] = Bs[kk + t + 4][col];
            }
            #pragma unroll
            for (int mi = 0; mi < 2; mi++) {
                #pragma unroll
                for (int ni = 0; ni < 4; ni++) {
                    asm volatile(
                        "mma.sync.aligned.m16n8k8.row.col.f32.tf32.tf32.f32 "
                        "{%0,%1,%2,%3}, {%4,%5,%6,%7}, {%8,%9}, {%0,%1,%2,%3};"
                        : "+f"(acc[mi][ni][0]), "+f"(acc[mi][ni][1]),
                          "+f"(acc[mi][ni][2]), "+f"(acc[mi][ni][3])
                        : "r"(afr[mi][0]), "r"(afr[mi][1]),
                          "r"(afr[mi][2]), "r"(afr[mi][3]),
                          "r"(bfr[ni][0]), "r"(bfr[ni][1]));
                }
            }
        }
        __syncthreads();
    }

    // epilogue: c0,c1 -> (row, col), (row, col+1); c2,c3 -> row+8
    #pragma unroll
    for (int mi = 0; mi < 2; mi++) {
        int row = bm + warpM * 32 + mi * 16 + g;
        float g0 = gate ? gate[row]     : 1.0f;
        float g1 = gate ? gate[row + 8] : 1.0f;
        #pragma unroll
        for (int ni = 0; ni < 4; ni++) {
            int col = bn + warpN * 32 + ni * 8 + 2 * t;
            if (col < N) {
                float bx = bias ? bias[col]     : 0.f;
                float by = bias ? bias[col + 1] : 0.f;
                float2 o0, o1;
                o0.x = acc[mi][ni][0] * g0 + bx;
                o0.y = acc[mi][ni][1] * g0 + by;
                o1.x = acc[mi][ni][2] * g1 + bx;
                o1.y = acc[mi][ni][3] * g1 + by;
                *(float2*)&Cout[(size_t)row * ldc + col]       = o0;
                *(float2*)&Cout[(size_t)(row + 8) * ldc + col] = o1;
            }
        }
    }
}

// ---------------------------------------------------------------------------
// Window attention. One block = (window, head, batch*branch).
// 128 tokens per window (8x16 or 16x8), head dim 24, online softmax.
// ---------------------------------------------------------------------------
__global__ __launch_bounds__(128) void win_attn(
    const float* __restrict__ q, const float* __restrict__ k,
    const float* __restrict__ v, float* __restrict__ out)
{
    __shared__ float Ks[128][DD];
    __shared__ float Vs[128][DD];

    const int wid  = blockIdx.x;      // 0..127 window within image+branch
    const int head = blockIdx.y;      // 0..3
    const int z    = blockIdx.z;      // 0..15
    const int b  = z >> 1;
    const int br = z & 1;

    const int Hs  = br ? 16 : 8;
    const int Wsp = br ? 8 : 16;
    const int nWw = WW / Wsp;
    const int wy = wid / nWw, wx = wid % nWw;
    const int h0 = wy * Hs, w0 = wx * Wsp;
    const int cb = br * CHH + head * DD;
    const int tid = threadIdx.x;

    // cooperative K,V load
    for (int idx = tid; idx < 128 * DD; idx += 128) {
        int t = idx / DD, d = idx - t * DD;
        int hs = t / Wsp, ws = t - hs * Wsp;
        int l = (h0 + hs) * WW + (w0 + ws);
        size_t base = ((size_t)b * LL + l) * CC + cb + d;
        Ks[t][d] = k[base];
        Vs[t][d] = v[base];
    }
    __syncthreads();

    // own query row
    const int hs = tid / Wsp, ws = tid - hs * Wsp;
    const int l = (h0 + hs) * WW + (w0 + ws);
    const size_t qbase = ((size_t)b * LL + l) * CC + cb;

    float qreg[DD];
    #pragma unroll
    for (int d = 0; d < DD; d++) qreg[d] = q[qbase + d] * SCALE;

    float mrun = -1e30f, lsum = 0.f;
    float acc[DD];
    #pragma unroll
    for (int d = 0; d < DD; d++) acc[d] = 0.f;

    for (int j = 0; j < 128; j++) {
        float s = 0.f;
        #pragma unroll
        for (int d = 0; d < DD; d++) s += qreg[d] * Ks[j][d];
        if (s > mrun) {                       // rare after warm-up
            float corr = __expf(mrun - s);
            lsum *= corr;
            #pragma unroll
            for (int d = 0; d < DD; d++) acc[d] *= corr;
            mrun = s;
        }
        float p = __expf(s - mrun);
        lsum += p;
        #pragma unroll
        for (int d = 0; d < DD; d++) acc[d] += p * Vs[j][d];
    }

    float inv = 1.f / lsum;
    #pragma unroll
    for (int d = 0; d < DD; d++) out[qbase + d] = acc[d] * inv;
}

// ---------------------------------------------------------------------------
// Depthwise 3x3 conv (SAME) + bias + BN + exact GELU, channel-last layout.
// ---------------------------------------------------------------------------
__global__ __launch_bounds__(256) void dwconv_bn_gelu(
    const float* __restrict__ x, const float* __restrict__ wgt,
    const float* __restrict__ wb,
    const float* __restrict__ g1, const float* __restrict__ b1,
    const float* __restrict__ m1, const float* __restrict__ v1r,
    float* __restrict__ out)
{
    int idx = blockIdx.x * 256 + threadIdx.x;
    if (idx >= MM * CC) return;
    int c = idx % CC;
    int rem = idx / CC;
    int l = rem % LL;
    int b = rem / LL;
    int h = l >> 7, w = l & 127;

    float acc = 0.f;
    #pragma unroll
    for (int kh = 0; kh < 3; kh++) {
        int hh = h + kh - 1;
        if ((unsigned)hh >= (unsigned)HH) continue;
        #pragma unroll
        for (int kw = 0; kw < 3; kw++) {
            int ww = w + kw - 1;
            if ((unsigned)ww >= (unsigned)WW) continue;
            acc += x[((size_t)b * LL + hh * WW + ww) * CC + c] * wgt[c * 9 + kh * 3 + kw];
        }
    }
    acc += wb[c];
    float sc = g1[c] * rsqrtf(v1r[c] + EPSV);
    float t = (acc - m1[c]) * sc + b1[c];
    out[idx] = 0.5f * t * (1.f + erff(t * 0.70710678118654752f));
}

// ---------------------------------------------------------------------------
// Transpose si_w1 (96,192) -> (192,96) so the 1x1 conv runs through the GEMM.
// ---------------------------------------------------------------------------
__global__ void transpose_w1(const float* __restrict__ w1, float* __restrict__ w1t)
{
    int idx = blockIdx.x * 256 + threadIdx.x;
    if (idx >= 96 * 192) return;
    int j = idx / 192, c = idx - j * 192;
    w1t[c * 96 + j] = w1[idx];
}

// ---------------------------------------------------------------------------
// gate[m] = sigmoid( sum_j si_w2[j] * gelu(bn2(hid[m,j])) + si_b2 )
// ---------------------------------------------------------------------------
__global__ __launch_bounds__(128) void gate_kernel(
    const float* __restrict__ hid,
    const float* __restrict__ g2, const float* __restrict__ b2,
    const float* __restrict__ m2, const float* __restrict__ v2r,
    const float* __restrict__ w2, const float* __restrict__ sb2,
    float* __restrict__ gate)
{
    int m = blockIdx.x * 4 + (threadIdx.x >> 5);
    int lane = threadIdx.x & 31;
    float sum = 0.f;
    #pragma unroll
    for (int jj = 0; jj < 3; jj++) {
        int j = lane + jj * 32;
        float t = hid[(size_t)m * 96 + j];
        float sc = g2[j] * rsqrtf(v2r[j] + EPSV);
        t = (t - m2[j]) * sc + b2[j];
        t = 0.5f * t * (1.f + erff(t * 0.70710678118654752f));
        sum += t * w2[j];
    }
    #pragma unroll
    for (int o = 16; o; o >>= 1) sum += __shfl_xor_sync(0xffffffffu, sum, o);
    if (lane == 0) {
        float s = sum + sb2[0];
        gate[m] = 1.f / (1.f + __expf(-s));
    }
}

// ---------------------------------------------------------------------------
extern "C" void kernel_launch(void* const* d_in, const int* in_sizes, int n_in,
                              void* d_out, int out_size)
{
    const float* x     = (const float*)d_in[0];
    const float* y     = (const float*)d_in[1];
    const float* Wqkv  = (const float*)d_in[2];
    const float* bqkv  = (const float*)d_in[3];
    const float* dw_w  = (const float*)d_in[4];
    const float* dw_b  = (const float*)d_in[5];
    const float* bn1_g = (const float*)d_in[6];
    const float* bn1_b = (const float*)d_in[7];
    const float* bn1_m = (const float*)d_in[8];
    const float* bn1_v = (const float*)d_in[9];
    const float* si_w1 = (const float*)d_in[10];
    const float* si_b1 = (const float*)d_in[11];
    const float* bn2_g = (const float*)d_in[12];
    const float* bn2_b = (const float*)d_in[13];
    const float* bn2_m = (const float*)d_in[14];
    const float* bn2_v = (const float*)d_in[15];
    const float* si_w2 = (const float*)d_in[16];
    const float* si_b2 = (const float*)d_in[17];
    const float* projw = (const float*)d_in[18];
    const float* projb = (const float*)d_in[19];

    float* scratch = nullptr;
    cudaGetSymbolAddress((void**)&scratch, g_scratch);

    float* q1   = scratch + OFF_Q1;
    float* v1   = scratch + OFF_V1;
    float* k2   = scratch + OFF_K2;
    float* v2   = scratch + OFF_V2;
    float* att  = scratch + OFF_ATT;
    float* conv = scratch + OFF_CONV;
    float* hid  = scratch + OFF_HID;
    float* gate = scratch + OFF_GATE;
    float* w1t  = scratch + OFF_W1T;

    dim3 gemmGrid(MM / 128, 3);

    // qkv projections (only the 4 needed slices)
    mma_gemm192<<<gemmGrid, 256>>>(x, CC, Wqkv + 0,       3 * CC, bqkv + 0,       nullptr, q1, CC, CC);
    mma_gemm192<<<gemmGrid, 256>>>(x, CC, Wqkv + 2 * CC,  3 * CC, bqkv + 2 * CC,  nullptr, v1, CC, CC);
    mma_gemm192<<<gemmGrid, 256>>>(y, CC, Wqkv + CC,      3 * CC, bqkv + CC,      nullptr, k2, CC, CC);
    mma_gemm192<<<gemmGrid, 256>>>(y, CC, Wqkv + 2 * CC,  3 * CC, bqkv + 2 * CC,  nullptr, v2, CC, CC);

    // window attention (both branches, all heads)
    win_attn<<<dim3(128, NHH, BB * 2), 128>>>(q1, k2, v1, att);

    // conv gating path on v2
    dwconv_bn_gelu<<<(MM * CC + 255) / 256, 256>>>(v2, dw_w, dw_b,
                                                   bn1_g, bn1_b, bn1_m, bn1_v, conv);
    transpose_w1<<<(96 * 192 + 255) / 256, 256>>>(si_w1, w1t);
    mma_gemm192<<<dim3(MM / 128, 2), 256>>>(conv, CC, w1t, 96, si_b1, nullptr, hid, 96, 96);
    gate_kernel<<<MM / 4, 128>>>(hid, bn2_g, bn2_b, bn2_m, bn2_v, si_w2, si_b2, gate);

    // final projection with fused per-row sigmoid gate
    mma_gemm192<<<gemmGrid, 256>>>(att, CC, projw, CC, projb, gate, (float*)d_out, CC, CC);
}

// round 7
// speedup vs baseline: 1.7507x; 1.1213x over previous
#include <cuda_runtime.h>
#include <math.h>
#include <stdint.h>

// Problem constants (fixed by the bench: B=8, H=W=128, C=192, split=(8,16), heads=8)
#define BB   8
#define HH   128
#define WW   128
#define CC   192
#define LL   (HH * WW)          // 16384
#define MM   (BB * LL)          // 131072 rows
#define CHH  96                 // C/2 per branch
#define NHH  4                  // heads per branch
#define DD   24                 // head dim
#define EPSV 1e-5f
#define SCALE 0.20412414523193154f   // 24^-0.5

// ---------------------------------------------------------------------------
// Scratch arena (no allocations allowed). Offsets in floats.
// ---------------------------------------------------------------------------
#define OFF_Q1   ((size_t)0)
#define OFF_V1   (OFF_Q1  + (size_t)MM * CC)
#define OFF_K2   (OFF_V1  + (size_t)MM * CC)
#define OFF_V2   (OFF_K2  + (size_t)MM * CC)
#define OFF_ATT  (OFF_V2  + (size_t)MM * CC)
#define OFF_CONV (OFF_ATT + (size_t)MM * CC)
#define OFF_HID  (OFF_CONV + (size_t)MM * CC)
#define OFF_GATE (OFF_HID + (size_t)MM * 96)
#define OFF_W1T  (OFF_GATE + (size_t)MM)
#define SCRATCH_FLOATS (OFF_W1T + (size_t)192 * 96)

__device__ float g_scratch[SCRATCH_FLOATS];

__device__ __forceinline__ uint32_t f2tf32(float f) {
    uint32_t u;
    asm("cvt.rna.tf32.f32 %0, %1;" : "=r"(u) : "f"(f));
    return u;
}

__device__ __forceinline__ void cpa16(uint32_t saddr, const void* gptr) {
    asm volatile("cp.async.cg.shared.global [%0], [%1], 16;" :: "r"(saddr), "l"(gptr));
}
__device__ __forceinline__ void cpa_commit() {
    asm volatile("cp.async.commit_group;");
}
__device__ __forceinline__ void cpa_wait0() {
    asm volatile("cp.async.wait_group 0;");
}

// ---------------------------------------------------------------------------
// TF32 tensor-core GEMM, K fixed at 192, full-width N block.
//   C[m,n] = gate[m] * (A[m,:] @ B[:,n]) + bias[n]
// Block tile 128 x (32*NI) [NI=6 -> 192, NI=3 -> 96], BK=16, 256 threads
// = 8 warps (2 in M x 4 in N), warp tile 64 x (NI*8): mi=4, ni=NI.
// grid.y == 1 -> A is read exactly once from DRAM (no N-block re-reads).
// cp.async double-buffered smem, one __syncthreads per K step.
// tf32 rounding happens on fragment registers (ALU pipe), raw fp32 in smem.
// Bank-conflict-free: As row stride 20 (g*20+t distinct mod 32),
//                     Bs row stride BN+8 (t*8+g distinct mod 32).
// ---------------------------------------------------------------------------
template<int NI>
__global__ __launch_bounds__(256, 1) void tc_gemm(
    const float* __restrict__ A, int lda,
    const float* __restrict__ Bm, int ldb,
    const float* __restrict__ bias,
    const float* __restrict__ gate,
    float* __restrict__ Cout, int ldc)
{
    constexpr int BN   = 32 * NI;      // 192 or 96
    constexpr int BSTR = BN + 8;       // 200 or 104  (stride%32==8, 16B-aligned)
    constexpr int NB4  = BN / 4;       // float4 columns of B tile

    __shared__ __align__(16) float As[2][128][20];
    __shared__ __align__(16) float Bs[2][16][BSTR];

    const int tid  = threadIdx.x;
    const int warp = tid >> 5;
    const int lane = tid & 31;
    const int g = lane >> 2;           // 0..7
    const int t = lane & 3;            // 0..3

    const int warpM = warp & 1;        // 0..1 -> 64-row slab
    const int warpN = warp >> 1;       // 0..3 -> (NI*8)-col slab
    const int bm = blockIdx.x * 128;

    // ---- cp.async task mappings ----
    // A tile: 128 rows x 16 cols = 512 float4 tasks, 2 per thread
    const int a_row0 = tid >> 1;                 // task tid
    const int a_c0   = (tid & 1) << 3;           // (tid&1)*2 f4 -> col 0 or 8
    // (task tid+256): row = a_row0+128? no: (tid+256)>>1 = a_row0+128 -> out of range.
    // Use (row, c4) = (task>>2, task&3): task0=tid, task1=tid+256.
    const int ar0 = tid >> 2,         ac0 = (tid & 3) << 2;
    const int ar1 = (tid + 256) >> 2, ac1 = ((tid + 256) & 3) << 2;

    const float* Ag0 = A + (size_t)(bm + ar0) * lda + ac0;
    const float* Ag1 = A + (size_t)(bm + ar1) * lda + ac1;

    float acc[4][NI][4];
    #pragma unroll
    for (int mi = 0; mi < 4; mi++)
        #pragma unroll
        for (int ni = 0; ni < NI; ni++)
            #pragma unroll
            for (int r = 0; r < 4; r++) acc[mi][ni][r] = 0.f;

    // ---- prologue: stage k0 = 0 into buffer 0 ----
    {
        cpa16((uint32_t)__cvta_generic_to_shared(&As[0][ar0][ac0]), Ag0);
        cpa16((uint32_t)__cvta_generic_to_shared(&As[0][ar1][ac1]), Ag1);
        #pragma unroll
        for (int j = 0; j < (16 * NB4 + 255) / 256; j++) {
            int task = tid + j * 256;
            if (task < 16 * NB4) {
                int br = task / NB4, bc = (task % NB4) * 4;
                cpa16((uint32_t)__cvta_generic_to_shared(&Bs[0][br][bc]),
                      Bm + (size_t)br * ldb + bc);
            }
        }
        cpa_commit();
    }

    for (int i = 0; i < 12; i++) {
        const int buf = i & 1;
        cpa_wait0();            // group i complete (only group pending)
        __syncthreads();        // data visible to all; prior compute done -> buffer safe

        if (i + 1 < 12) {       // prefetch k0 of step i+1 into other buffer
            const int nb = buf ^ 1;
            const int k0 = (i + 1) * 16;
            cpa16((uint32_t)__cvta_generic_to_shared(&As[nb][ar0][ac0]), Ag0 + k0);
            cpa16((uint32_t)__cvta_generic_to_shared(&As[nb][ar1][ac1]), Ag1 + k0);
            #pragma unroll
            for (int j = 0; j < (16 * NB4 + 255) / 256; j++) {
                int task = tid + j * 256;
                if (task < 16 * NB4) {
                    int br = task / NB4, bc = (task % NB4) * 4;
                    cpa16((uint32_t)__cvta_generic_to_shared(&Bs[nb][br][bc]),
                          Bm + (size_t)(k0 + br) * ldb + bc);
                }
            }
            cpa_commit();
        }

        // ---- compute on buffer buf ----
        #pragma unroll
        for (int kk = 0; kk < 16; kk += 8) {
            uint32_t afr[4][4];
            #pragma unroll
            for (int mi = 0; mi < 4; mi++) {
                int row = warpM * 64 + mi * 16 + g;
                afr[mi][0] = f2tf32(As[buf][row    ][kk + t    ]);
                afr[mi][1] = f2tf32(As[buf][row + 8][kk + t    ]);
                afr[mi][2] = f2tf32(As[buf][row    ][kk + t + 4]);
                afr[mi][3] = f2tf32(As[buf][row + 8][kk + t + 4]);
            }
            uint32_t bfr[NI][2];
            #pragma unroll
            for (int ni = 0; ni < NI; ni++) {
                int col = warpN * (NI * 8) + ni * 8 + g;
                bfr[ni][0] = f2tf32(Bs[buf][kk + t    ][col]);
                bfr[ni][1] = f2tf32(Bs[buf][kk + t + 4][col]);
            }
            #pragma unroll
            for (int mi = 0; mi < 4; mi++) {
                #pragma unroll
                for (int ni = 0; ni < NI; ni++) {
                    asm volatile(
                        "mma.sync.aligned.m16n8k8.row.col.f32.tf32.tf32.f32 "
                        "{%0,%1,%2,%3}, {%4,%5,%6,%7}, {%8,%9}, {%0,%1,%2,%3};"
                        : "+f"(acc[mi][ni][0]), "+f"(acc[mi][ni][1]),
                          "+f"(acc[mi][ni][2]), "+f"(acc[mi][ni][3])
                        : "r"(afr[mi][0]), "r"(afr[mi][1]),
                          "r"(afr[mi][2]), "r"(afr[mi][3]),
                          "r"(bfr[ni][0]), "r"(bfr[ni][1]));
                }
            }
        }
    }

    // ---- epilogue (block N == problem N exactly: no guards) ----
    #pragma unroll
    for (int mi = 0; mi < 4; mi++) {
        int row = bm + warpM * 64 + mi * 16 + g;
        float g0 = gate ? gate[row]     : 1.0f;
        float g1 = gate ? gate[row + 8] : 1.0f;
        #pragma unroll
        for (int ni = 0; ni < NI; ni++) {
            int col = warpN * (NI * 8) + ni * 8 + 2 * t;
            float bx = bias ? bias[col]     : 0.f;
            float by = bias ? bias[col + 1] : 0.f;
            float2 o0, o1;
            o0.x = acc[mi][ni][0] * g0 + bx;
            o0.y = acc[mi][ni][1] * g0 + by;
            o1.x = acc[mi][ni][2] * g1 + bx;
            o1.y = acc[mi][ni][3] * g1 + by;
            *(float2*)&Cout[(size_t)row * ldc + col]       = o0;
            *(float2*)&Cout[(size_t)(row + 8) * ldc + col] = o1;
        }
    }
}

// ---------------------------------------------------------------------------
// Window attention. One block = (window, head, batch*branch).
// 128 tokens per window (8x16 or 16x8), head dim 24, online softmax.
// K/V rows are 96B (float4-aligned): inner loop reads float4.
// ---------------------------------------------------------------------------
__global__ __launch_bounds__(128) void win_attn(
    const float* __restrict__ q, const float* __restrict__ k,
    const float* __restrict__ v, float* __restrict__ out)
{
    __shared__ __align__(16) float Ks[128][DD];
    __shared__ __align__(16) float Vs[128][DD];

    const int wid  = blockIdx.x;      // 0..127 window within image+branch
    const int head = blockIdx.y;      // 0..3
    const int z    = blockIdx.z;      // 0..15
    const int b  = z >> 1;
    const int br = z & 1;

    const int Hs  = br ? 16 : 8;
    const int Wsp = br ? 8 : 16;
    const int nWw = WW / Wsp;
    const int wy = wid / nWw, wx = wid % nWw;
    const int h0 = wy * Hs, w0 = wx * Wsp;
    const int cb = br * CHH + head * DD;
    const int tid = threadIdx.x;

    // cooperative K,V load: thread t loads row t (24 floats = 6 float4)
    {
        int hs = tid / Wsp, ws = tid - hs * Wsp;
        int l = (h0 + hs) * WW + (w0 + ws);
        const float* kp = k + ((size_t)b * LL + l) * CC + cb;
        const float* vp = v + ((size_t)b * LL + l) * CC + cb;
        #pragma unroll
        for (int d4 = 0; d4 < 6; d4++) {
            *(float4*)&Ks[tid][d4 * 4] = *(const float4*)(kp + d4 * 4);
            *(float4*)&Vs[tid][d4 * 4] = *(const float4*)(vp + d4 * 4);
        }
    }
    __syncthreads();

    // own query row
    const int hs = tid / Wsp, ws = tid - hs * Wsp;
    const int l = (h0 + hs) * WW + (w0 + ws);
    const size_t qbase = ((size_t)b * LL + l) * CC + cb;

    float qreg[DD];
    #pragma unroll
    for (int d = 0; d < DD; d++) qreg[d] = q[qbase + d] * SCALE;

    float mrun = -1e30f, lsum = 0.f;
    float acc[DD];
    #pragma unroll
    for (int d = 0; d < DD; d++) acc[d] = 0.f;

    #pragma unroll 2
    for (int j = 0; j < 128; j++) {
        float s = 0.f;
        #pragma unroll
        for (int d4 = 0; d4 < 6; d4++) {
            float4 kv = *(const float4*)&Ks[j][d4 * 4];
            s += qreg[d4 * 4 + 0] * kv.x + qreg[d4 * 4 + 1] * kv.y
               + qreg[d4 * 4 + 2] * kv.z + qreg[d4 * 4 + 3] * kv.w;
        }
        if (s > mrun) {                       // rare after warm-up
            float corr = __expf(mrun - s);
            lsum *= corr;
            #pragma unroll
            for (int d = 0; d < DD; d++) acc[d] *= corr;
            mrun = s;
        }
        float p = __expf(s - mrun);
        lsum += p;
        #pragma unroll
        for (int d4 = 0; d4 < 6; d4++) {
            float4 vv = *(const float4*)&Vs[j][d4 * 4];
            acc[d4 * 4 + 0] += p * vv.x;
            acc[d4 * 4 + 1] += p * vv.y;
            acc[d4 * 4 + 2] += p * vv.z;
            acc[d4 * 4 + 3] += p * vv.w;
        }
    }

    float inv = 1.f / lsum;
    #pragma unroll
    for (int d = 0; d < DD; d++) out[qbase + d] = acc[d] * inv;
}

// ---------------------------------------------------------------------------
// Depthwise 3x3 conv (SAME) + bias + BN + exact GELU, channel-last layout.
// ---------------------------------------------------------------------------
__global__ __launch_bounds__(256) void dwconv_bn_gelu(
    const float* __restrict__ x, const float* __restrict__ wgt,
    const float* __restrict__ wb,
    const float* __restrict__ g1, const float* __restrict__ b1,
    const float* __restrict__ m1, const float* __restrict__ v1r,
    float* __restrict__ out)
{
    int idx = blockIdx.x * 256 + threadIdx.x;
    if (idx >= MM * CC) return;
    int c = idx % CC;
    int rem = idx / CC;
    int l = rem % LL;
    int b = rem / LL;
    int h = l >> 7, w = l & 127;

    float acc = 0.f;
    #pragma unroll
    for (int kh = 0; kh < 3; kh++) {
        int hh = h + kh - 1;
        if ((unsigned)hh >= (unsigned)HH) continue;
        #pragma unroll
        for (int kw = 0; kw < 3; kw++) {
            int ww = w + kw - 1;
            if ((unsigned)ww >= (unsigned)WW) continue;
            acc += x[((size_t)b * LL + hh * WW + ww) * CC + c] * wgt[c * 9 + kh * 3 + kw];
        }
    }
    acc += wb[c];
    float sc = g1[c] * rsqrtf(v1r[c] + EPSV);
    float t = (acc - m1[c]) * sc + b1[c];
    out[idx] = 0.5f * t * (1.f + erff(t * 0.70710678118654752f));
}

// ---------------------------------------------------------------------------
// Transpose si_w1 (96,192) -> (192,96) so the 1x1 conv runs through the GEMM.
// ---------------------------------------------------------------------------
__global__ void transpose_w1(const float* __restrict__ w1, float* __restrict__ w1t)
{
    int idx = blockIdx.x * 256 + threadIdx.x;
    if (idx >= 96 * 192) return;
    int j = idx / 192, c = idx - j * 192;
    w1t[c * 96 + j] = w1[idx];
}

// ---------------------------------------------------------------------------
// gate[m] = sigmoid( sum_j si_w2[j] * gelu(bn2(hid[m,j])) + si_b2 )
// ---------------------------------------------------------------------------
__global__ __launch_bounds__(128) void gate_kernel(
    const float* __restrict__ hid,
    const float* __restrict__ g2, const float* __restrict__ b2,
    const float* __restrict__ m2, const float* __restrict__ v2r,
    const float* __restrict__ w2, const float* __restrict__ sb2,
    float* __restrict__ gate)
{
    int m = blockIdx.x * 4 + (threadIdx.x >> 5);
    int lane = threadIdx.x & 31;
    float sum = 0.f;
    #pragma unroll
    for (int jj = 0; jj < 3; jj++) {
        int j = lane + jj * 32;
        float t = hid[(size_t)m * 96 + j];
        float sc = g2[j] * rsqrtf(v2r[j] + EPSV);
        t = (t - m2[j]) * sc + b2[j];
        t = 0.5f * t * (1.f + erff(t * 0.70710678118654752f));
        sum += t * w2[j];
    }
    #pragma unroll
    for (int o = 16; o; o >>= 1) sum += __shfl_xor_sync(0xffffffffu, sum, o);
    if (lane == 0) {
        float s = sum + sb2[0];
        gate[m] = 1.f / (1.f + __expf(-s));
    }
}

// ---------------------------------------------------------------------------
extern "C" void kernel_launch(void* const* d_in, const int* in_sizes, int n_in,
                              void* d_out, int out_size)
{
    const float* x     = (const float*)d_in[0];
    const float* y     = (const float*)d_in[1];
    const float* Wqkv  = (const float*)d_in[2];
    const float* bqkv  = (const float*)d_in[3];
    const float* dw_w  = (const float*)d_in[4];
    const float* dw_b  = (const float*)d_in[5];
    const float* bn1_g = (const float*)d_in[6];
    const float* bn1_b = (const float*)d_in[7];
    const float* bn1_m = (const float*)d_in[8];
    const float* bn1_v = (const float*)d_in[9];
    const float* si_w1 = (const float*)d_in[10];
    const float* si_b1 = (const float*)d_in[11];
    const float* bn2_g = (const float*)d_in[12];
    const float* bn2_b = (const float*)d_in[13];
    const float* bn2_m = (const float*)d_in[14];
    const float* bn2_v = (const float*)d_in[15];
    const float* si_w2 = (const float*)d_in[16];
    const float* si_b2 = (const float*)d_in[17];
    const float* projw = (const float*)d_in[18];
    const float* projb = (const float*)d_in[19];

    float* scratch = nullptr;
    cudaGetSymbolAddress((void**)&scratch, g_scratch);

    float* q1   = scratch + OFF_Q1;
    float* v1   = scratch + OFF_V1;
    float* k2   = scratch + OFF_K2;
    float* v2   = scratch + OFF_V2;
    float* att  = scratch + OFF_ATT;
    float* conv = scratch + OFF_CONV;
    float* hid  = scratch + OFF_HID;
    float* gate = scratch + OFF_GATE;
    float* w1t  = scratch + OFF_W1T;

    const int gblk = MM / 128;   // 1024

    // qkv projections (only the 4 needed slices); full-width N=192 tiles
    tc_gemm<6><<<gblk, 256>>>(x, CC, Wqkv + 0,      3 * CC, bqkv + 0,      nullptr, q1, CC);
    tc_gemm<6><<<gblk, 256>>>(x, CC, Wqkv + 2 * CC, 3 * CC, bqkv + 2 * CC, nullptr, v1, CC);
    tc_gemm<6><<<gblk, 256>>>(y, CC, Wqkv + CC,     3 * CC, bqkv + CC,     nullptr, k2, CC);
    tc_gemm<6><<<gblk, 256>>>(y, CC, Wqkv + 2 * CC, 3 * CC, bqkv + 2 * CC, nullptr, v2, CC);

    // window attention (both branches, all heads)
    win_attn<<<dim3(128, NHH, BB * 2), 128>>>(q1, k2, v1, att);

    // conv gating path on v2
    dwconv_bn_gelu<<<(MM * CC + 255) / 256, 256>>>(v2, dw_w, dw_b,
                                                   bn1_g, bn1_b, bn1_m, bn1_v, conv);
    transpose_w1<<<(96 * 192 + 255) / 256, 256>>>(si_w1, w1t);
    tc_gemm<3><<<gblk, 256>>>(conv, CC, w1t, 96, si_b1, nullptr, hid, 96);
    gate_kernel<<<MM / 4, 128>>>(hid, bn2_g, bn2_b, bn2_m, bn2_v, si_w2, si_b2, gate);

    // final projection with fused per-row sigmoid gate
    tc_gemm<6><<<gblk, 256>>>(att, CC, projw, CC, projb, gate, (float*)d_out, CC);
}